// round 2
// baseline (speedup 1.0000x reference)
#include <cuda_runtime.h>
#include <math.h>

// Shapes fixed: B=8, C=32, H=W=256. irnn out channels = 128.
#define HW 65536

typedef unsigned long long u64;

__device__ float g_a [8ULL *  32 * 65536];   //  64 MB conv outputs (32ch)
__device__ float g_b4[8ULL * 128 * 65536];   // 256 MB irnn outputs (128ch)

// ---- packed f32x2 helpers (sm_103a FFMA2 path) ------------------------------
__device__ __forceinline__ u64 pack2(float lo, float hi) {
    u64 r; asm("mov.b64 %0, {%1, %2};" : "=l"(r) : "f"(lo), "f"(hi)); return r;
}
__device__ __forceinline__ void unpack2(u64 v, float& lo, float& hi) {
    asm("mov.b64 {%0, %1}, %2;" : "=f"(lo), "=f"(hi) : "l"(v));
}
__device__ __forceinline__ void ffma2(u64& d, u64 a, u64 b) {
    asm("fma.rn.f32x2 %0, %1, %2, %0;" : "+l"(d) : "l"(a), "l"(b));
}

// ---------------------------------------------------------------------------
// 3x3 SAME conv, Cout=32, fp32, packed-f32x2 math.
//  - 32x16 pixel tile per CTA, 256 threads, each thread owns 2 adjacent pixels
//  - accumulators are f32x2 (one FFMA2 = 2 pixel-FMAs)
//  - weights pre-splatted to f32x2 in smem: 9 pairs via 4xLDS.128 + 1xLDS.64
//  - input staged in smem in ci-chunks of 8 with halo
//  - FUSE_OUT folds relu + 1x1 conv + sigmoid into the epilogue
// ---------------------------------------------------------------------------
template<int CIN, bool FUSE_OUT>
__global__ __launch_bounds__(256)
void conv3x3_k(const float* __restrict__ in, const float* __restrict__ wgt,
               const float* __restrict__ wout, float* __restrict__ out)
{
    const int tx = threadIdx.x & 15;        // pixel-pair x
    const int ty = threadIdx.x >> 4;        // pixel y in tile
    const int w0 = blockIdx.x << 5;         // 32-wide tile
    const int h0 = blockIdx.y << 4;         // 16-tall tile
    const int b  = blockIdx.z;
    const int gw = w0 + 2 * tx, gh = h0 + ty;

    __shared__ __align__(16) float s_in[8 * 18 * 34];        // [ci][18][34]
    __shared__ __align__(16) u64   s_w [32 * 8 * 10];        // [co][ci][10] splatted

    u64 acc2[32];
#pragma unroll
    for (int i = 0; i < 32; i++) acc2[i] = 0ULL;

    const float* inb = in + (size_t)b * CIN * HW;

    for (int ci0 = 0; ci0 < CIN; ci0 += 8) {
        // stage weights, pre-splatted to f32x2 (stride 10 u64 = 80B, 16B aligned)
        for (int idx = threadIdx.x; idx < 32 * 8 * 10; idx += 256) {
            int co  = idx / 80;
            int r   = idx - co * 80;
            int cic = r / 10;
            int k   = r - cic * 10;
            float wv = (k < 9) ? wgt[(co * CIN + ci0 + cic) * 9 + k] : 0.f;
            s_w[idx] = pack2(wv, wv);
        }
        // stage input tile with halo (zero pad at border)
        for (int idx = threadIdx.x; idx < 8 * 612; idx += 256) {
            int cic = idx / 612;
            int rr  = idx - cic * 612;
            int r   = rr / 34;
            int cc  = rr - r * 34;
            int ih = h0 - 1 + r, iw = w0 - 1 + cc;
            float v = 0.f;
            if ((unsigned)ih < 256u && (unsigned)iw < 256u)
                v = inb[(size_t)(ci0 + cic) * HW + ih * 256 + iw];
            s_in[idx] = v;
        }
        __syncthreads();

#pragma unroll
        for (int cic = 0; cic < 8; cic++) {
            // 2-pixel neighborhood: 3 rows x 4 cols -> 9 packed pairs
            const float* t = &s_in[cic * 612 + ty * 34 + 2 * tx];
            u64 vp[9];
#pragma unroll
            for (int r = 0; r < 3; r++) {
                float a0 = t[r * 34 + 0], a1 = t[r * 34 + 1];
                float a2 = t[r * 34 + 2], a3 = t[r * 34 + 3];
                vp[r * 3 + 0] = pack2(a0, a1);
                vp[r * 3 + 1] = pack2(a1, a2);
                vp[r * 3 + 2] = pack2(a2, a3);
            }
            const u64* wbase = &s_w[cic * 10];
#pragma unroll
            for (int co = 0; co < 32; co++) {
                const u64* wb = wbase + co * 80;
                const ulonglong2* q = (const ulonglong2*)wb;
                ulonglong2 w01 = q[0], w23 = q[1], w45 = q[2], w67 = q[3];
                u64 w8 = wb[8];
                ffma2(acc2[co], vp[0], w01.x);
                ffma2(acc2[co], vp[1], w01.y);
                ffma2(acc2[co], vp[2], w23.x);
                ffma2(acc2[co], vp[3], w23.y);
                ffma2(acc2[co], vp[4], w45.x);
                ffma2(acc2[co], vp[5], w45.y);
                ffma2(acc2[co], vp[6], w67.x);
                ffma2(acc2[co], vp[7], w67.y);
                ffma2(acc2[co], vp[8], w8);
            }
        }
        __syncthreads();
    }

    if (FUSE_OUT) {
        float s0 = 0.f, s1 = 0.f;
#pragma unroll
        for (int co = 0; co < 32; co++) {
            float a, bb; unpack2(acc2[co], a, bb);
            float wv = __ldg(&wout[co]);
            s0 += fmaxf(a, 0.f) * wv;
            s1 += fmaxf(bb, 0.f) * wv;
        }
        float2 r;
        r.x = 1.0f / (1.0f + expf(-s0));
        r.y = 1.0f / (1.0f + expf(-s1));
        *(float2*)&out[(size_t)b * HW + gh * 256 + gw] = r;
    } else {
#pragma unroll
        for (int co = 0; co < 32; co++) {
            float a, bb; unpack2(acc2[co], a, bb);
            float2 r; r.x = a; r.y = bb;
            *(float2*)&out[(size_t)(b * 32 + co) * HW + gh * 256 + gw] = r;
        }
    }
}

// ---------------------------------------------------------------------------
// IRNN scan along H (axis 2). Thread = one (b, c, w) column; coalesced.
// ---------------------------------------------------------------------------
template<bool REV>
__global__ __launch_bounds__(256)
void scan_h(const float* __restrict__ in, float* __restrict__ out,
            const float* __restrict__ ws, const float* __restrict__ bs,
            int dir, int ch_off)
{
    int t = blockIdx.x * 256 + threadIdx.x;       // over B*C*W = 65536
    int wcoord = t & 255;
    int c = (t >> 8) & 31;
    int b = t >> 13;
    const float* ip = in  + (size_t)(b * 32  + c) * HW + wcoord;
    float*       op = out + (size_t)(b * 128 + ch_off + c) * HW + wcoord;
    float wc = ws[dir * 32 + c], bc = bs[dir * 32 + c];

    if (!REV) {
        float h = ip[0];
        op[0] = h;
#pragma unroll 4
        for (int y = 1; y < 256; y++) {
            h = fmaxf(wc * h + bc + ip[y * 256], 0.f);
            op[y * 256] = h;
        }
    } else {
        float h = ip[255 * 256];
        op[255 * 256] = h;
#pragma unroll 4
        for (int y = 254; y >= 0; y--) {
            h = fmaxf(wc * h + bc + ip[y * 256], 0.f);
            op[y * 256] = h;
        }
    }
}

// ---------------------------------------------------------------------------
// IRNN scan along W (axis 3). 32 rows of one (b,c) plane per block.
// Coalesced I/O via 32x33 smem transpose tile; warp 0 runs the recurrence.
// ---------------------------------------------------------------------------
template<bool REV>
__global__ __launch_bounds__(256)
void scan_w(const float* __restrict__ in, float* __restrict__ out,
            const float* __restrict__ ws, const float* __restrict__ bs,
            int dir, int ch_off)
{
    __shared__ float tile[32][33];
    int R0 = blockIdx.x * 32;                 // flat row index over (b, c, h)
    int c  = (R0 >> 8) & 31;
    int b  = R0 >> 13;
    int h0 = R0 & 255;
    float wc = ws[dir * 32 + c], bc = bs[dir * 32 + c];

    const float* ip = in + (size_t)R0 * 256;
    float* op = out + ((size_t)(b * 128 + ch_off + c) * 256 + h0) * 256;

    int lr   = threadIdx.x >> 5;
    int lcol = threadIdx.x & 31;

    float hstate = 0.f;
    for (int ch = 0; ch < 8; ch++) {
        int wc0 = REV ? (224 - ch * 32) : ch * 32;
#pragma unroll
        for (int i = 0; i < 4; i++) {
            int r = lr + i * 8;
            tile[r][lcol] = ip[r * 256 + wc0 + lcol];
        }
        __syncthreads();
        if (threadIdx.x < 32) {
            int r = threadIdx.x;
            float h = hstate;
            if (!REV) {
                for (int j = 0; j < 32; j++) {
                    float val = tile[r][j];
                    h = (ch == 0 && j == 0) ? val : fmaxf(wc * h + bc + val, 0.f);
                    tile[r][j] = h;
                }
            } else {
                for (int j = 31; j >= 0; j--) {
                    float val = tile[r][j];
                    h = (ch == 0 && j == 31) ? val : fmaxf(wc * h + bc + val, 0.f);
                    tile[r][j] = h;
                }
            }
            hstate = h;
        }
        __syncthreads();
#pragma unroll
        for (int i = 0; i < 4; i++) {
            int r = lr + i * 8;
            op[r * 256 + wc0 + lcol] = tile[r][lcol];
        }
        __syncthreads();
    }
}

// ---------------------------------------------------------------------------
extern "C" void kernel_launch(void* const* d_in, const int* in_sizes, int n_in,
                              void* d_out, int out_size)
{
    const float* x   = (const float*)d_in[0];
    const float* w1  = (const float*)d_in[1];
    const float* w2  = (const float*)d_in[2];
    const float* w3  = (const float*)d_in[3];
    const float* wo  = (const float*)d_in[4];
    const float* i1w = (const float*)d_in[5];
    const float* i1b = (const float*)d_in[6];
    const float* i2w = (const float*)d_in[7];
    const float* i2b = (const float*)d_in[8];
    float* outp = (float*)d_out;

    float *ga, *gb;
    cudaGetSymbolAddress((void**)&ga, g_a);
    cudaGetSymbolAddress((void**)&gb, g_b4);

    dim3 cg(8, 16, 8);   // 32x16 pixel tiles

    conv3x3_k<32,  false><<<cg, 256>>>(x,  w1, nullptr, ga);

    scan_h<true ><<<256,  256>>>(ga, gb, i1w, i1b, 0,  0);   // up
    scan_w<false><<<2048, 256>>>(ga, gb, i1w, i1b, 1, 32);   // right
    scan_h<false><<<256,  256>>>(ga, gb, i1w, i1b, 2, 64);   // down
    scan_w<true ><<<2048, 256>>>(ga, gb, i1w, i1b, 3, 96);   // left

    conv3x3_k<128, false><<<cg, 256>>>(gb, w2, nullptr, ga);

    scan_h<true ><<<256,  256>>>(ga, gb, i2w, i2b, 0,  0);
    scan_w<false><<<2048, 256>>>(ga, gb, i2w, i2b, 1, 32);
    scan_h<false><<<256,  256>>>(ga, gb, i2w, i2b, 2, 64);
    scan_w<true ><<<2048, 256>>>(ga, gb, i2w, i2b, 3, 96);

    conv3x3_k<128, true ><<<cg, 256>>>(gb, w3, wo, outp);
}

// round 4
// speedup vs baseline: 2.8232x; 2.8232x over previous
#include <cuda_runtime.h>
#include <cuda_bf16.h>
#include <math.h>
#include <stdint.h>

#define HW 65536

// ---------------------------------------------------------------------------
// Scratch (no allocations allowed)
// ---------------------------------------------------------------------------
__device__ float          g_f32[8ULL * 65536 * 32];    //  64 MB NHWC fp32 conv outputs
__device__ __nv_bfloat16  g_hi [8ULL * 65536 * 128];   // 128 MB NHWC bf16 hi
__device__ __nv_bfloat16  g_lo [8ULL * 65536 * 128];   // 128 MB NHWC bf16 lo
__device__ __align__(16) char g_wb[334848];            // prepped B (padded row-major, hi|lo)
// conv1: hi@0      lo@18944   (BSTR=592,  32 rows)
// conv2: hi@37888  lo@112128  (BSTR=2320, 32 rows)
// conv3: hi@186368 lo@260608

// ---------------------------------------------------------------------------
__device__ __forceinline__ uint32_t smem_u32(const void* p) {
    uint32_t a;
    asm("{ .reg .u64 t; cvta.to.shared.u64 t, %1; cvt.u32.u64 %0, t; }" : "=r"(a) : "l"(p));
    return a;
}
__device__ __forceinline__ uint32_t lds32(uint32_t a) {
    uint32_t v; asm volatile("ld.shared.b32 %0, [%1];" : "=r"(v) : "r"(a)); return v;
}
__device__ __forceinline__ void ldm4(uint32_t* r, uint32_t a) {
    asm volatile("ldmatrix.sync.aligned.m8n8.x4.shared.b16 {%0,%1,%2,%3}, [%4];"
                 : "=r"(r[0]), "=r"(r[1]), "=r"(r[2]), "=r"(r[3]) : "r"(a));
}
__device__ __forceinline__ void mma16816(float* c, const uint32_t* a, uint32_t b0, uint32_t b1) {
    asm volatile("mma.sync.aligned.m16n8k16.row.col.f32.bf16.bf16.f32 "
        "{%0,%1,%2,%3}, {%4,%5,%6,%7}, {%8,%9}, {%0,%1,%2,%3};"
        : "+f"(c[0]), "+f"(c[1]), "+f"(c[2]), "+f"(c[3])
        : "r"(a[0]), "r"(a[1]), "r"(a[2]), "r"(a[3]), "r"(b0), "r"(b1));
}

// ---------------------------------------------------------------------------
// Weight prep: fp32 [32][CIN][3][3] -> bf16 hi/lo padded row-major B images.
// k = dyi*3*CIN + dxi*CIN + c ; row stride = 9*CIN*2 + 16 bytes (pad zeroed).
// ---------------------------------------------------------------------------
__global__ void prep_w(const float* __restrict__ w, char* __restrict__ bhi,
                       char* __restrict__ blo, int CIN)
{
    int K = 9 * CIN, KP = K + 8, BSTR = K * 2 + 16;
    int idx = blockIdx.x * 256 + threadIdx.x;
    if (idx >= 32 * KP) return;
    int n = idx / KP, k = idx - n * KP;
    float v = 0.f;
    if (k < K) {
        int dyi = k / (3 * CIN);
        int r   = k - dyi * 3 * CIN;
        int dxi = r / CIN;
        int c   = r - dxi * CIN;
        v = w[(n * CIN + c) * 9 + dyi * 3 + dxi];
    }
    __nv_bfloat16 hi = __float2bfloat16(v);
    __nv_bfloat16 lo = __float2bfloat16(v - __bfloat162float(hi));
    int o = n * BSTR + k * 2;
    *(__nv_bfloat16*)(bhi + o) = hi;
    *(__nv_bfloat16*)(blo + o) = lo;
}

// ---------------------------------------------------------------------------
// x (NCHW fp32) -> NHWC bf16 hi/lo (32 ch)
// ---------------------------------------------------------------------------
__global__ __launch_bounds__(256)
void transpose_x(const float* __restrict__ x, __nv_bfloat16* __restrict__ ohi,
                 __nv_bfloat16* __restrict__ olo)
{
    __shared__ float t[32][33];
    int b = blockIdx.y;
    int p0 = blockIdx.x * 32;
    int lane = threadIdx.x & 31, grp = threadIdx.x >> 5;
#pragma unroll
    for (int i = 0; i < 4; i++) {
        int c = grp + i * 8;
        t[c][lane] = x[((size_t)b * 32 + c) * HW + p0 + lane];
    }
    __syncthreads();
#pragma unroll
    for (int i = 0; i < 4; i++) {
        int p = grp + i * 8;
        float v = t[lane][p];
        __nv_bfloat16 hi = __float2bfloat16(v);
        __nv_bfloat16 lo = __float2bfloat16(v - __bfloat162float(hi));
        size_t o = ((size_t)b * HW + p0 + p) * 32 + lane;
        ohi[o] = hi; olo[o] = lo;
    }
}

// ---------------------------------------------------------------------------
// HMMA implicit-GEMM 3x3 conv.  CTA = 128 pixels (half row) x 32 couts.
// 8 warps, each m16 tile. A: NHWC bf16 hi/lo staged per-dy into padded smem;
// B: prepped padded row-major in g_wb, copied to smem once.
// Split-3: acc += Ahi*Bhi + Alo*Bhi + Ahi*Blo (fp32 accumulators).
// ---------------------------------------------------------------------------
template<int CIN, bool FUSE>
__global__ __launch_bounds__(256, 1)
void conv_mma(const __nv_bfloat16* __restrict__ ahi, const __nv_bfloat16* __restrict__ alo,
              const char* __restrict__ wb, const float* __restrict__ wout,
              float* __restrict__ out)
{
    constexpr int K     = 9 * CIN;
    constexpr int ASTR  = CIN * 2 + 16;        // A row stride (bytes) — bank-spread pad
    constexpr int BSTR  = K * 2 + 16;          // B row stride (bytes)
    constexpr int BBYT  = 32 * BSTR;           // one split's B image
    constexpr int V4    = CIN / 8;             // uint4 per pixel-row
    constexpr int ABYT  = 130 * ASTR;

    extern __shared__ __align__(16) char smem[];
    // [Bhi BBYT][Blo BBYT][Ahi ABYT][Alo ABYT]
    const int tid  = threadIdx.x;
    const int lane = tid & 31;
    const int wid  = tid >> 5;
    const int w0   = blockIdx.x << 7;
    const int h    = blockIdx.y;
    const int b    = blockIdx.z;

    const uint32_t s0   = smem_u32(smem);
    const uint32_t sBhi = s0;
    const uint32_t sBlo = s0 + BBYT;
    const uint32_t sAhi = s0 + 2 * BBYT;
    const uint32_t sAlo = sAhi + ABYT;

    // copy B (hi|lo contiguous) into smem
    {
        const uint4* src = (const uint4*)wb;
        uint4* dst = (uint4*)smem;
        const int n4 = 2 * BBYT / 16;
        for (int i = tid; i < n4; i += 256) dst[i] = src[i];
    }

    const int m0 = wid * 16;
    const uint32_t aRowOff = (uint32_t)(lane & 15) * ASTR + ((lane & 16) ? 16u : 0u);
    const uint32_t bOff    = (uint32_t)(lane >> 2) * BSTR + (uint32_t)(lane & 3) * 4;

    float acc[16];
#pragma unroll
    for (int i = 0; i < 16; i++) acc[i] = 0.f;

    for (int dy = 0; dy < 3; dy++) {
        const int hh = h + dy - 1;
        const bool hok = (unsigned)hh < 256u;
        __syncthreads();
        // stage A row [130 px][CIN] hi+lo with zero-fill halo
        {
            const size_t rowbase = ((size_t)b * HW + (size_t)(hok ? hh : 0) * 256);
            for (int i = tid; i < 130 * V4; i += 256) {
                int px = i / V4, v = i - px * V4;
                int w  = w0 - 1 + px;
                uint4 vh = make_uint4(0, 0, 0, 0), vl = vh;
                if (hok && (unsigned)w < 256u) {
                    const uint4* ph = (const uint4*)(ahi + (rowbase + w) * CIN) + v;
                    const uint4* pl = (const uint4*)(alo + (rowbase + w) * CIN) + v;
                    vh = *ph; vl = *pl;
                }
                *(uint4*)(smem + 2 * BBYT + px * ASTR + v * 16)        = vh;
                *(uint4*)(smem + 2 * BBYT + ABYT + px * ASTR + v * 16) = vl;
            }
        }
        __syncthreads();

#pragma unroll
        for (int dx = 0; dx < 3; dx++) {
#pragma unroll
            for (int kc = 0; kc < CIN / 16; kc++) {
                uint32_t ah[4], al[4];
                const uint32_t abase = (uint32_t)(m0 + dx) * ASTR + kc * 32 + aRowOff;
                ldm4(ah, sAhi + abase);
                ldm4(al, sAlo + abase);
                const uint32_t kb = (uint32_t)(dy * 3 * CIN + dx * CIN + kc * 16) * 2;
#pragma unroll
                for (int nt = 0; nt < 4; nt++) {
                    const uint32_t ba = bOff + (uint32_t)nt * 8 * BSTR + kb;
                    uint32_t bh0 = lds32(sBhi + ba), bh1 = lds32(sBhi + ba + 16);
                    uint32_t bl0 = lds32(sBlo + ba), bl1 = lds32(sBlo + ba + 16);
                    mma16816(acc + nt * 4, ah, bh0, bh1);
                    mma16816(acc + nt * 4, al, bh0, bh1);
                    mma16816(acc + nt * 4, ah, bl0, bl1);
                }
            }
        }
    }

    // epilogue
    const int prow = m0 + (lane >> 2);
    if (!FUSE) {
        float* ob = out + ((size_t)b * HW + (size_t)h * 256 + w0) * 32;
#pragma unroll
        for (int nt = 0; nt < 4; nt++) {
            int ch = nt * 8 + (lane & 3) * 2;
            *(float2*)(ob + (size_t)prow * 32 + ch)       = make_float2(acc[nt * 4 + 0], acc[nt * 4 + 1]);
            *(float2*)(ob + (size_t)(prow + 8) * 32 + ch) = make_float2(acc[nt * 4 + 2], acc[nt * 4 + 3]);
        }
    } else {
        float s0v = 0.f, s1v = 0.f;
#pragma unroll
        for (int nt = 0; nt < 4; nt++) {
            int ch = nt * 8 + (lane & 3) * 2;
            float wa = __ldg(&wout[ch]), wb2 = __ldg(&wout[ch + 1]);
            s0v += fmaxf(acc[nt * 4 + 0], 0.f) * wa + fmaxf(acc[nt * 4 + 1], 0.f) * wb2;
            s1v += fmaxf(acc[nt * 4 + 2], 0.f) * wa + fmaxf(acc[nt * 4 + 3], 0.f) * wb2;
        }
        s0v += __shfl_xor_sync(0xffffffffu, s0v, 1);
        s0v += __shfl_xor_sync(0xffffffffu, s0v, 2);
        s1v += __shfl_xor_sync(0xffffffffu, s1v, 1);
        s1v += __shfl_xor_sync(0xffffffffu, s1v, 2);
        if ((lane & 3) == 0) {
            size_t ob = (size_t)b * HW + (size_t)h * 256 + w0;
            out[ob + prow]     = 1.0f / (1.0f + expf(-s0v));
            out[ob + prow + 8] = 1.0f / (1.0f + expf(-s1v));
        }
    }
}

// ---------------------------------------------------------------------------
// IRNN scans: NHWC fp32 in (32 ch) -> bf16 hi/lo NHWC 128ch @ ch_off.
// t0 output is raw x; then h = relu(w*h + b + x).
// ---------------------------------------------------------------------------
template<bool REV>
__global__ __launch_bounds__(256)
void scan_hk(const float* __restrict__ in, __nv_bfloat16* __restrict__ ohi,
             __nv_bfloat16* __restrict__ olo, const float* __restrict__ ws,
             const float* __restrict__ bs, int dir, int ch_off)
{
    int t = blockIdx.x * 256 + threadIdx.x;      // over B*W*C = 65536
    int c = t & 31, w = (t >> 5) & 255, b = t >> 13;
    const float* ip = in + (size_t)b * HW * 32 + (size_t)w * 32 + c;
    size_t ob = (size_t)b * HW * 128 + (size_t)w * 128 + ch_off + c;
    float wc = ws[dir * 32 + c], bc = bs[dir * 32 + c];

    float hst = REV ? ip[(size_t)255 * 8192] : ip[0];
    {
        size_t o = ob + (size_t)(REV ? 255 : 0) * 32768;
        __nv_bfloat16 hi = __float2bfloat16(hst);
        ohi[o] = hi; olo[o] = __float2bfloat16(hst - __bfloat162float(hi));
    }
#pragma unroll 4
    for (int i = 1; i < 256; i++) {
        int y = REV ? (255 - i) : i;
        hst = fmaxf(wc * hst + bc + ip[(size_t)y * 8192], 0.f);
        size_t o = ob + (size_t)y * 32768;
        __nv_bfloat16 hi = __float2bfloat16(hst);
        ohi[o] = hi; olo[o] = __float2bfloat16(hst - __bfloat162float(hi));
    }
}

template<bool REV>
__global__ __launch_bounds__(256)
void scan_wk(const float* __restrict__ in, __nv_bfloat16* __restrict__ ohi,
             __nv_bfloat16* __restrict__ olo, const float* __restrict__ ws,
             const float* __restrict__ bs, int dir, int ch_off)
{
    int t = blockIdx.x * 256 + threadIdx.x;      // over B*H*C = 65536
    int c = t & 31, h = (t >> 5) & 255, b = t >> 13;
    const float* ip = in + (size_t)b * HW * 32 + (size_t)h * 8192 + c;
    size_t ob = (size_t)b * HW * 128 + (size_t)h * 32768 + ch_off + c;
    float wc = ws[dir * 32 + c], bc = bs[dir * 32 + c];

    float hst = REV ? ip[255 * 32] : ip[0];
    {
        size_t o = ob + (size_t)(REV ? 255 : 0) * 128;
        __nv_bfloat16 hi = __float2bfloat16(hst);
        ohi[o] = hi; olo[o] = __float2bfloat16(hst - __bfloat162float(hi));
    }
#pragma unroll 4
    for (int i = 1; i < 256; i++) {
        int w = REV ? (255 - i) : i;
        hst = fmaxf(wc * hst + bc + ip[w * 32], 0.f);
        size_t o = ob + (size_t)w * 128;
        __nv_bfloat16 hi = __float2bfloat16(hst);
        ohi[o] = hi; olo[o] = __float2bfloat16(hst - __bfloat162float(hi));
    }
}

// ---------------------------------------------------------------------------
extern "C" void kernel_launch(void* const* d_in, const int* in_sizes, int n_in,
                              void* d_out, int out_size)
{
    const float* x   = (const float*)d_in[0];
    const float* w1  = (const float*)d_in[1];
    const float* w2  = (const float*)d_in[2];
    const float* w3  = (const float*)d_in[3];
    const float* wo  = (const float*)d_in[4];
    const float* i1w = (const float*)d_in[5];
    const float* i1b = (const float*)d_in[6];
    const float* i2w = (const float*)d_in[7];
    const float* i2b = (const float*)d_in[8];
    float* outp = (float*)d_out;

    float* gf;  __nv_bfloat16 *ghi, *glo;  char* gwb;
    cudaGetSymbolAddress((void**)&gf,  g_f32);
    cudaGetSymbolAddress((void**)&ghi, g_hi);
    cudaGetSymbolAddress((void**)&glo, g_lo);
    cudaGetSymbolAddress((void**)&gwb, g_wb);

    // smem: conv1 = 2*18944 + 2*130*80  = 58688
    //       conv2/3 = 2*74240 + 2*130*272 = 219200
    cudaFuncSetAttribute(conv_mma<32,  false>, cudaFuncAttributeMaxDynamicSharedMemorySize, 58688);
    cudaFuncSetAttribute(conv_mma<128, false>, cudaFuncAttributeMaxDynamicSharedMemorySize, 219200);
    cudaFuncSetAttribute(conv_mma<128, true >, cudaFuncAttributeMaxDynamicSharedMemorySize, 219200);

    // prep B weight images
    prep_w<<<(32 * 296  + 255) / 256, 256>>>(w1, gwb + 0,      gwb + 18944,  32);
    prep_w<<<(32 * 1160 + 255) / 256, 256>>>(w2, gwb + 37888,  gwb + 112128, 128);
    prep_w<<<(32 * 1160 + 255) / 256, 256>>>(w3, gwb + 186368, gwb + 260608, 128);

    // x -> NHWC bf16 split (32 ch)
    transpose_x<<<dim3(2048, 8), 256>>>(x, ghi, glo);

    dim3 cg(2, 256, 8);
    conv_mma<32, false><<<cg, 256, 58688>>>(ghi, glo, gwb + 0, nullptr, gf);

    scan_hk<true ><<<256, 256>>>(gf, ghi, glo, i1w, i1b, 0,  0);   // up
    scan_wk<false><<<256, 256>>>(gf, ghi, glo, i1w, i1b, 1, 32);   // right
    scan_hk<false><<<256, 256>>>(gf, ghi, glo, i1w, i1b, 2, 64);   // down
    scan_wk<true ><<<256, 256>>>(gf, ghi, glo, i1w, i1b, 3, 96);   // left

    conv_mma<128, false><<<cg, 256, 219200>>>(ghi, glo, gwb + 37888, nullptr, gf);

    scan_hk<true ><<<256, 256>>>(gf, ghi, glo, i2w, i2b, 0,  0);
    scan_wk<false><<<256, 256>>>(gf, ghi, glo, i2w, i2b, 1, 32);
    scan_hk<false><<<256, 256>>>(gf, ghi, glo, i2w, i2b, 2, 64);
    scan_wk<true ><<<256, 256>>>(gf, ghi, glo, i2w, i2b, 3, 96);

    conv_mma<128, true><<<cg, 256, 219200>>>(ghi, glo, gwb + 186368, wo, outp);
}

// round 5
// speedup vs baseline: 3.3727x; 1.1946x over previous
#include <cuda_runtime.h>
#include <cuda_bf16.h>
#include <math.h>
#include <stdint.h>

#define HW 65536

// ---------------------------------------------------------------------------
// Scratch (no allocations allowed)
// ---------------------------------------------------------------------------
__device__ float          g_f32[8ULL * 65536 * 32];    //  64 MB NHWC fp32 conv outputs
__device__ __nv_bfloat16  g_hi [8ULL * 65536 * 128];   // 128 MB NHWC bf16 hi
__device__ __nv_bfloat16  g_lo [8ULL * 65536 * 128];   // 128 MB NHWC bf16 lo
__device__ __align__(16) char g_wb[334848];            // prepped B (padded row-major, hi|lo)
// conv1: hi@0      lo@18944   (BSTR=592,  32 rows)
// conv2: hi@37888  lo@112128  (BSTR=2320, 32 rows)
// conv3: hi@186368 lo@260608

// ---------------------------------------------------------------------------
__device__ __forceinline__ uint32_t smem_u32(const void* p) {
    uint32_t a;
    asm("{ .reg .u64 t; cvta.to.shared.u64 t, %1; cvt.u32.u64 %0, t; }" : "=r"(a) : "l"(p));
    return a;
}
__device__ __forceinline__ uint32_t lds32(uint32_t a) {
    uint32_t v; asm volatile("ld.shared.b32 %0, [%1];" : "=r"(v) : "r"(a)); return v;
}
__device__ __forceinline__ void ldm4(uint32_t* r, uint32_t a) {
    asm volatile("ldmatrix.sync.aligned.m8n8.x4.shared.b16 {%0,%1,%2,%3}, [%4];"
                 : "=r"(r[0]), "=r"(r[1]), "=r"(r[2]), "=r"(r[3]) : "r"(a));
}
__device__ __forceinline__ void mma16816(float* c, const uint32_t* a, uint32_t b0, uint32_t b1) {
    asm volatile("mma.sync.aligned.m16n8k16.row.col.f32.bf16.bf16.f32 "
        "{%0,%1,%2,%3}, {%4,%5,%6,%7}, {%8,%9}, {%0,%1,%2,%3};"
        : "+f"(c[0]), "+f"(c[1]), "+f"(c[2]), "+f"(c[3])
        : "r"(a[0]), "r"(a[1]), "r"(a[2]), "r"(a[3]), "r"(b0), "r"(b1));
}

// ---------------------------------------------------------------------------
// Weight prep: fp32 [32][CIN][3][3] -> bf16 hi/lo padded row-major B images.
// ---------------------------------------------------------------------------
__global__ void prep_w(const float* __restrict__ w, char* __restrict__ bhi,
                       char* __restrict__ blo, int CIN)
{
    int K = 9 * CIN, KP = K + 8, BSTR = K * 2 + 16;
    int idx = blockIdx.x * 256 + threadIdx.x;
    if (idx >= 32 * KP) return;
    int n = idx / KP, k = idx - n * KP;
    float v = 0.f;
    if (k < K) {
        int dyi = k / (3 * CIN);
        int r   = k - dyi * 3 * CIN;
        int dxi = r / CIN;
        int c   = r - dxi * CIN;
        v = w[(n * CIN + c) * 9 + dyi * 3 + dxi];
    }
    __nv_bfloat16 hi = __float2bfloat16(v);
    __nv_bfloat16 lo = __float2bfloat16(v - __bfloat162float(hi));
    int o = n * BSTR + k * 2;
    *(__nv_bfloat16*)(bhi + o) = hi;
    *(__nv_bfloat16*)(blo + o) = lo;
}

// ---------------------------------------------------------------------------
// x (NCHW fp32) -> NHWC bf16 hi/lo (32 ch)
// ---------------------------------------------------------------------------
__global__ __launch_bounds__(256)
void transpose_x(const float* __restrict__ x, __nv_bfloat16* __restrict__ ohi,
                 __nv_bfloat16* __restrict__ olo)
{
    __shared__ float t[32][33];
    int b = blockIdx.y;
    int p0 = blockIdx.x * 32;
    int lane = threadIdx.x & 31, grp = threadIdx.x >> 5;
#pragma unroll
    for (int i = 0; i < 4; i++) {
        int c = grp + i * 8;
        t[c][lane] = x[((size_t)b * 32 + c) * HW + p0 + lane];
    }
    __syncthreads();
#pragma unroll
    for (int i = 0; i < 4; i++) {
        int p = grp + i * 8;
        float v = t[lane][p];
        __nv_bfloat16 hi = __float2bfloat16(v);
        __nv_bfloat16 lo = __float2bfloat16(v - __bfloat162float(hi));
        size_t o = ((size_t)b * HW + p0 + p) * 32 + lane;
        ohi[o] = hi; olo[o] = lo;
    }
}

// ---------------------------------------------------------------------------
// HMMA implicit-GEMM 3x3 conv, 2 output rows per CTA.
// CTA = 2 rows x 128 px x 32 couts.  8 warps, each owns one m16 pixel range
// in BOTH rows (A fragment reused).  Loop over 4 input rows; each staged A
// row feeds both output rows with their dy-slice of B.
// Split-3: acc += Ahi*Bhi + Alo*Bhi + Ahi*Blo (fp32 accumulators).
// ---------------------------------------------------------------------------
template<int CIN, bool FUSE>
__global__ __launch_bounds__(256, 1)
void conv_mma(const __nv_bfloat16* __restrict__ ahi, const __nv_bfloat16* __restrict__ alo,
              const char* __restrict__ wb, const float* __restrict__ wout,
              float* __restrict__ out)
{
    constexpr int K     = 9 * CIN;
    constexpr int ASTR  = CIN * 2 + 16;        // A row stride (bytes)
    constexpr int BSTR  = K * 2 + 16;          // B row stride (bytes)
    constexpr int BBYT  = 32 * BSTR;           // one split's B image
    constexpr int V4    = CIN / 8;             // uint4 per pixel-row
    constexpr int ABYT  = 130 * ASTR;          // one input row (one split)

    extern __shared__ __align__(16) char smem[];
    // [Bhi BBYT][Blo BBYT][Ahi ABYT][Alo ABYT]
    const int tid  = threadIdx.x;
    const int lane = tid & 31;
    const int wid  = tid >> 5;
    const int w0   = blockIdx.x << 7;
    const int h0   = blockIdx.y << 1;          // first of 2 output rows
    const int b    = blockIdx.z;

    const uint32_t s0   = smem_u32(smem);
    const uint32_t sBhi = s0;
    const uint32_t sBlo = s0 + BBYT;
    const uint32_t sAhi = s0 + 2 * BBYT;
    const uint32_t sAlo = sAhi + ABYT;

    // copy B (hi|lo contiguous) into smem
    {
        const uint4* src = (const uint4*)wb;
        uint4* dst = (uint4*)smem;
        const int n4 = 2 * BBYT / 16;
        for (int i = tid; i < n4; i += 256) dst[i] = src[i];
    }

    const int m0 = wid * 16;
    const uint32_t aRowOff = (uint32_t)(lane & 15) * ASTR + ((lane & 16) ? 16u : 0u);
    const uint32_t bOff    = (uint32_t)(lane >> 2) * BSTR + (uint32_t)(lane & 3) * 4;

    float acc[2][16];
#pragma unroll
    for (int r = 0; r < 2; r++)
#pragma unroll
        for (int i = 0; i < 16; i++) acc[r][i] = 0.f;

    for (int s = 0; s < 4; s++) {
        const int ir = h0 - 1 + s;                 // input row
        if ((unsigned)ir >= 256u) { __syncthreads(); __syncthreads(); continue; }
        const int dy0 = s;                          // dy for output row h0   (valid if <=2)
        const int dy1 = s - 1;                      // dy for output row h0+1 (valid if >=0)

        __syncthreads();
        // stage A row [130 px][CIN] hi+lo with zero-fill w-halo
        {
            const size_t rowbase = ((size_t)b * HW + (size_t)ir * 256);
            for (int i = tid; i < 130 * V4; i += 256) {
                int px = i / V4, v = i - px * V4;
                int w  = w0 - 1 + px;
                uint4 vh = make_uint4(0, 0, 0, 0), vl = vh;
                if ((unsigned)w < 256u) {
                    vh = *((const uint4*)(ahi + (rowbase + w) * CIN) + v);
                    vl = *((const uint4*)(alo + (rowbase + w) * CIN) + v);
                }
                *(uint4*)(smem + 2 * BBYT + px * ASTR + v * 16)        = vh;
                *(uint4*)(smem + 2 * BBYT + ABYT + px * ASTR + v * 16) = vl;
            }
        }
        __syncthreads();

#pragma unroll
        for (int dx = 0; dx < 3; dx++) {
#pragma unroll
            for (int kc = 0; kc < CIN / 16; kc++) {
                uint32_t ah[4], al[4];
                const uint32_t abase = (uint32_t)(m0 + dx) * ASTR + kc * 32 + aRowOff;
                ldm4(ah, sAhi + abase);
                ldm4(al, sAlo + abase);
#pragma unroll
                for (int r = 0; r < 2; r++) {
                    const int dy = (r == 0) ? dy0 : dy1;
                    if (dy < 0 || dy > 2) continue;
                    const uint32_t kb = (uint32_t)(dy * 3 * CIN + dx * CIN + kc * 16) * 2;
#pragma unroll
                    for (int nt = 0; nt < 4; nt++) {
                        const uint32_t ba = bOff + (uint32_t)nt * 8 * BSTR + kb;
                        uint32_t bh0 = lds32(sBhi + ba), bh1 = lds32(sBhi + ba + 16);
                        uint32_t bl0 = lds32(sBlo + ba), bl1 = lds32(sBlo + ba + 16);
                        mma16816(acc[r] + nt * 4, ah, bh0, bh1);
                        mma16816(acc[r] + nt * 4, al, bh0, bh1);
                        mma16816(acc[r] + nt * 4, ah, bl0, bl1);
                    }
                }
            }
        }
    }

    // epilogue (both rows)
    const int prow = m0 + (lane >> 2);
#pragma unroll
    for (int r = 0; r < 2; r++) {
        const int h = h0 + r;
        if (!FUSE) {
            float* ob = out + ((size_t)b * HW + (size_t)h * 256 + w0) * 32;
#pragma unroll
            for (int nt = 0; nt < 4; nt++) {
                int ch = nt * 8 + (lane & 3) * 2;
                *(float2*)(ob + (size_t)prow * 32 + ch)       = make_float2(acc[r][nt * 4 + 0], acc[r][nt * 4 + 1]);
                *(float2*)(ob + (size_t)(prow + 8) * 32 + ch) = make_float2(acc[r][nt * 4 + 2], acc[r][nt * 4 + 3]);
            }
        } else {
            float s0v = 0.f, s1v = 0.f;
#pragma unroll
            for (int nt = 0; nt < 4; nt++) {
                int ch = nt * 8 + (lane & 3) * 2;
                float wa = __ldg(&wout[ch]), wb2 = __ldg(&wout[ch + 1]);
                s0v += fmaxf(acc[r][nt * 4 + 0], 0.f) * wa + fmaxf(acc[r][nt * 4 + 1], 0.f) * wb2;
                s1v += fmaxf(acc[r][nt * 4 + 2], 0.f) * wa + fmaxf(acc[r][nt * 4 + 3], 0.f) * wb2;
            }
            s0v += __shfl_xor_sync(0xffffffffu, s0v, 1);
            s0v += __shfl_xor_sync(0xffffffffu, s0v, 2);
            s1v += __shfl_xor_sync(0xffffffffu, s1v, 1);
            s1v += __shfl_xor_sync(0xffffffffu, s1v, 2);
            if ((lane & 3) == 0) {
                size_t ob = (size_t)b * HW + (size_t)h * 256 + w0;
                out[ob + prow]     = 1.0f / (1.0f + expf(-s0v));
                out[ob + prow + 8] = 1.0f / (1.0f + expf(-s1v));
            }
        }
    }
}

// ---------------------------------------------------------------------------
// IRNN scans: NHWC fp32 in (32 ch) -> bf16 hi/lo NHWC 128ch @ ch_off.
// ---------------------------------------------------------------------------
template<bool REV>
__global__ __launch_bounds__(256)
void scan_hk(const float* __restrict__ in, __nv_bfloat16* __restrict__ ohi,
             __nv_bfloat16* __restrict__ olo, const float* __restrict__ ws,
             const float* __restrict__ bs, int dir, int ch_off)
{
    int t = blockIdx.x * 256 + threadIdx.x;      // over B*W*C = 65536
    int c = t & 31, w = (t >> 5) & 255, b = t >> 13;
    const float* ip = in + (size_t)b * HW * 32 + (size_t)w * 32 + c;
    size_t ob = (size_t)b * HW * 128 + (size_t)w * 128 + ch_off + c;
    float wc = ws[dir * 32 + c], bc = bs[dir * 32 + c];

    float hst = REV ? ip[(size_t)255 * 8192] : ip[0];
    {
        size_t o = ob + (size_t)(REV ? 255 : 0) * 32768;
        __nv_bfloat16 hi = __float2bfloat16(hst);
        ohi[o] = hi; olo[o] = __float2bfloat16(hst - __bfloat162float(hi));
    }
#pragma unroll 8
    for (int i = 1; i < 256; i++) {
        int y = REV ? (255 - i) : i;
        hst = fmaxf(wc * hst + bc + ip[(size_t)y * 8192], 0.f);
        size_t o = ob + (size_t)y * 32768;
        __nv_bfloat16 hi = __float2bfloat16(hst);
        ohi[o] = hi; olo[o] = __float2bfloat16(hst - __bfloat162float(hi));
    }
}

template<bool REV>
__global__ __launch_bounds__(256)
void scan_wk(const float* __restrict__ in, __nv_bfloat16* __restrict__ ohi,
             __nv_bfloat16* __restrict__ olo, const float* __restrict__ ws,
             const float* __restrict__ bs, int dir, int ch_off)
{
    int t = blockIdx.x * 256 + threadIdx.x;      // over B*H*C = 65536
    int c = t & 31, h = (t >> 5) & 255, b = t >> 13;
    const float* ip = in + (size_t)b * HW * 32 + (size_t)h * 8192 + c;
    size_t ob = (size_t)b * HW * 128 + (size_t)h * 32768 + ch_off + c;
    float wc = ws[dir * 32 + c], bc = bs[dir * 32 + c];

    float hst = REV ? ip[255 * 32] : ip[0];
    {
        size_t o = ob + (size_t)(REV ? 255 : 0) * 128;
        __nv_bfloat16 hi = __float2bfloat16(hst);
        ohi[o] = hi; olo[o] = __float2bfloat16(hst - __bfloat162float(hi));
    }
#pragma unroll 8
    for (int i = 1; i < 256; i++) {
        int w = REV ? (255 - i) : i;
        hst = fmaxf(wc * hst + bc + ip[w * 32], 0.f);
        size_t o = ob + (size_t)w * 128;
        __nv_bfloat16 hi = __float2bfloat16(hst);
        ohi[o] = hi; olo[o] = __float2bfloat16(hst - __bfloat162float(hi));
    }
}

// ---------------------------------------------------------------------------
extern "C" void kernel_launch(void* const* d_in, const int* in_sizes, int n_in,
                              void* d_out, int out_size)
{
    const float* x   = (const float*)d_in[0];
    const float* w1  = (const float*)d_in[1];
    const float* w2  = (const float*)d_in[2];
    const float* w3  = (const float*)d_in[3];
    const float* wo  = (const float*)d_in[4];
    const float* i1w = (const float*)d_in[5];
    const float* i1b = (const float*)d_in[6];
    const float* i2w = (const float*)d_in[7];
    const float* i2b = (const float*)d_in[8];
    float* outp = (float*)d_out;

    float* gf;  __nv_bfloat16 *ghi, *glo;  char* gwb;
    cudaGetSymbolAddress((void**)&gf,  g_f32);
    cudaGetSymbolAddress((void**)&ghi, g_hi);
    cudaGetSymbolAddress((void**)&glo, g_lo);
    cudaGetSymbolAddress((void**)&gwb, g_wb);

    // smem: conv1 = 2*18944 + 2*10400 = 58688 ; conv2/3 = 2*74240 + 2*35360 = 219200
    cudaFuncSetAttribute(conv_mma<32,  false>, cudaFuncAttributeMaxDynamicSharedMemorySize, 58688);
    cudaFuncSetAttribute(conv_mma<128, false>, cudaFuncAttributeMaxDynamicSharedMemorySize, 219200);
    cudaFuncSetAttribute(conv_mma<128, true >, cudaFuncAttributeMaxDynamicSharedMemorySize, 219200);

    // prep B weight images
    prep_w<<<(32 * 296  + 255) / 256, 256>>>(w1, gwb + 0,      gwb + 18944,  32);
    prep_w<<<(32 * 1160 + 255) / 256, 256>>>(w2, gwb + 37888,  gwb + 112128, 128);
    prep_w<<<(32 * 1160 + 255) / 256, 256>>>(w3, gwb + 186368, gwb + 260608, 128);

    // x -> NHWC bf16 split (32 ch)
    transpose_x<<<dim3(2048, 8), 256>>>(x, ghi, glo);

    dim3 cg(2, 128, 8);   // 2 output rows per CTA
    conv_mma<32, false><<<cg, 256, 58688>>>(ghi, glo, gwb + 0, nullptr, gf);

    scan_hk<true ><<<256, 256>>>(gf, ghi, glo, i1w, i1b, 0,  0);   // up
    scan_wk<false><<<256, 256>>>(gf, ghi, glo, i1w, i1b, 1, 32);   // right
    scan_hk<false><<<256, 256>>>(gf, ghi, glo, i1w, i1b, 2, 64);   // down
    scan_wk<true ><<<256, 256>>>(gf, ghi, glo, i1w, i1b, 3, 96);   // left

    conv_mma<128, false><<<cg, 256, 219200>>>(ghi, glo, gwb + 37888, nullptr, gf);

    scan_hk<true ><<<256, 256>>>(gf, ghi, glo, i2w, i2b, 0,  0);
    scan_wk<false><<<256, 256>>>(gf, ghi, glo, i2w, i2b, 1, 32);
    scan_hk<false><<<256, 256>>>(gf, ghi, glo, i2w, i2b, 2, 64);
    scan_wk<true ><<<256, 256>>>(gf, ghi, glo, i2w, i2b, 3, 96);

    conv_mma<128, true><<<cg, 256, 219200>>>(ghi, glo, gwb + 186368, wo, outp);
}

// round 6
// speedup vs baseline: 3.6104x; 1.0705x over previous
#include <cuda_runtime.h>
#include <cuda_bf16.h>
#include <math.h>
#include <stdint.h>

#define HW 65536

// ---------------------------------------------------------------------------
// Scratch (no allocations allowed)
// ---------------------------------------------------------------------------
__device__ float          g_f32[8ULL * 65536 * 32];    //  64 MB NHWC fp32 conv outputs
__device__ __nv_bfloat16  g_hi [8ULL * 65536 * 128];   // 128 MB NHWC bf16 hi
__device__ __nv_bfloat16  g_lo [8ULL * 65536 * 128];   // 128 MB NHWC bf16 lo
__device__ __align__(16) char g_wb[334848];            // prepped B (padded row-major, hi|lo)
// conv1: hi@0      lo@18944   (BSTR=592,  32 rows)
// conv2: hi@37888  lo@112128  (BSTR=2320, 32 rows)
// conv3: hi@186368 lo@260608

// ---------------------------------------------------------------------------
__device__ __forceinline__ uint32_t smem_u32(const void* p) {
    uint32_t a;
    asm("{ .reg .u64 t; cvta.to.shared.u64 t, %1; cvt.u32.u64 %0, t; }" : "=r"(a) : "l"(p));
    return a;
}
__device__ __forceinline__ uint32_t lds32(uint32_t a) {
    uint32_t v; asm volatile("ld.shared.b32 %0, [%1];" : "=r"(v) : "r"(a)); return v;
}
__device__ __forceinline__ void ldm4(uint32_t* r, uint32_t a) {
    asm volatile("ldmatrix.sync.aligned.m8n8.x4.shared.b16 {%0,%1,%2,%3}, [%4];"
                 : "=r"(r[0]), "=r"(r[1]), "=r"(r[2]), "=r"(r[3]) : "r"(a));
}
__device__ __forceinline__ void mma16816(float* c, const uint32_t* a, uint32_t b0, uint32_t b1) {
    asm volatile("mma.sync.aligned.m16n8k16.row.col.f32.bf16.bf16.f32 "
        "{%0,%1,%2,%3}, {%4,%5,%6,%7}, {%8,%9}, {%0,%1,%2,%3};"
        : "+f"(c[0]), "+f"(c[1]), "+f"(c[2]), "+f"(c[3])
        : "r"(a[0]), "r"(a[1]), "r"(a[2]), "r"(a[3]), "r"(b0), "r"(b1));
}

// ---------------------------------------------------------------------------
// Weight prep: fp32 [32][CIN][3][3] -> bf16 hi/lo padded row-major B images.
// ---------------------------------------------------------------------------
__global__ void prep_w(const float* __restrict__ w, char* __restrict__ bhi,
                       char* __restrict__ blo, int CIN)
{
    int K = 9 * CIN, KP = K + 8, BSTR = K * 2 + 16;
    int idx = blockIdx.x * 256 + threadIdx.x;
    if (idx >= 32 * KP) return;
    int n = idx / KP, k = idx - n * KP;
    float v = 0.f;
    if (k < K) {
        int dyi = k / (3 * CIN);
        int r   = k - dyi * 3 * CIN;
        int dxi = r / CIN;
        int c   = r - dxi * CIN;
        v = w[(n * CIN + c) * 9 + dyi * 3 + dxi];
    }
    __nv_bfloat16 hi = __float2bfloat16(v);
    __nv_bfloat16 lo = __float2bfloat16(v - __bfloat162float(hi));
    int o = n * BSTR + k * 2;
    *(__nv_bfloat16*)(bhi + o) = hi;
    *(__nv_bfloat16*)(blo + o) = lo;
}

// ---------------------------------------------------------------------------
// x (NCHW fp32) -> NHWC bf16 hi/lo (32 ch)
// ---------------------------------------------------------------------------
__global__ __launch_bounds__(256)
void transpose_x(const float* __restrict__ x, __nv_bfloat16* __restrict__ ohi,
                 __nv_bfloat16* __restrict__ olo)
{
    __shared__ float t[32][33];
    int b = blockIdx.y;
    int p0 = blockIdx.x * 32;
    int lane = threadIdx.x & 31, grp = threadIdx.x >> 5;
#pragma unroll
    for (int i = 0; i < 4; i++) {
        int c = grp + i * 8;
        t[c][lane] = x[((size_t)b * 32 + c) * HW + p0 + lane];
    }
    __syncthreads();
#pragma unroll
    for (int i = 0; i < 4; i++) {
        int p = grp + i * 8;
        float v = t[lane][p];
        __nv_bfloat16 hi = __float2bfloat16(v);
        __nv_bfloat16 lo = __float2bfloat16(v - __bfloat162float(hi));
        size_t o = ((size_t)b * HW + p0 + p) * 32 + lane;
        ohi[o] = hi; olo[o] = lo;
    }
}

// ---------------------------------------------------------------------------
// HMMA implicit-GEMM 3x3 conv, 4 output rows per CTA.
// CTA = 4 rows x 128 px x 32 couts.  8 warps, each owns one m16 pixel range
// across ALL 4 rows (A fragment reused for up to 3 rows per stage).
// Loop over 6 input rows; each staged row feeds rows r with dy = s - r in [0,2].
// Split-3: acc += Ahi*Bhi + Alo*Bhi + Ahi*Blo (fp32 accumulators).
// ---------------------------------------------------------------------------
template<int CIN, bool FUSE>
__global__ __launch_bounds__(256, 1)
void conv_mma(const __nv_bfloat16* __restrict__ ahi, const __nv_bfloat16* __restrict__ alo,
              const char* __restrict__ wb, const float* __restrict__ wout,
              float* __restrict__ out)
{
    constexpr int K     = 9 * CIN;
    constexpr int ASTR  = CIN * 2 + 16;        // A row stride (bytes)
    constexpr int BSTR  = K * 2 + 16;          // B row stride (bytes)
    constexpr int BBYT  = 32 * BSTR;           // one split's B image
    constexpr int V4    = CIN / 8;             // uint4 per pixel-row
    constexpr int ABYT  = 130 * ASTR;          // one input row (one split)

    extern __shared__ __align__(16) char smem[];
    // [Bhi BBYT][Blo BBYT][Ahi ABYT][Alo ABYT]
    const int tid  = threadIdx.x;
    const int lane = tid & 31;
    const int wid  = tid >> 5;
    const int w0   = blockIdx.x << 7;
    const int h0   = blockIdx.y << 2;          // first of 4 output rows
    const int b    = blockIdx.z;

    const uint32_t s0   = smem_u32(smem);
    const uint32_t sBhi = s0;
    const uint32_t sBlo = s0 + BBYT;
    const uint32_t sAhi = s0 + 2 * BBYT;
    const uint32_t sAlo = sAhi + ABYT;

    // copy B (hi|lo contiguous) into smem
    {
        const uint4* src = (const uint4*)wb;
        uint4* dst = (uint4*)smem;
        const int n4 = 2 * BBYT / 16;
        for (int i = tid; i < n4; i += 256) dst[i] = src[i];
    }

    const int m0 = wid * 16;
    const uint32_t aRowOff = (uint32_t)(lane & 15) * ASTR + ((lane & 16) ? 16u : 0u);
    const uint32_t bOff    = (uint32_t)(lane >> 2) * BSTR + (uint32_t)(lane & 3) * 4;

    float acc[4][16];
#pragma unroll
    for (int r = 0; r < 4; r++)
#pragma unroll
        for (int i = 0; i < 16; i++) acc[r][i] = 0.f;

    for (int s = 0; s < 6; s++) {
        const int ir = h0 - 1 + s;                 // input row
        __syncthreads();
        if ((unsigned)ir < 256u) {
            // stage A row [130 px][CIN] hi+lo with zero-fill w-halo
            const size_t rowbase = ((size_t)b * HW + (size_t)ir * 256);
            for (int i = tid; i < 130 * V4; i += 256) {
                int px = i / V4, v = i - px * V4;
                int w  = w0 - 1 + px;
                uint4 vh = make_uint4(0, 0, 0, 0), vl = vh;
                if ((unsigned)w < 256u) {
                    vh = *((const uint4*)(ahi + (rowbase + w) * CIN) + v);
                    vl = *((const uint4*)(alo + (rowbase + w) * CIN) + v);
                }
                *(uint4*)(smem + 2 * BBYT + px * ASTR + v * 16)        = vh;
                *(uint4*)(smem + 2 * BBYT + ABYT + px * ASTR + v * 16) = vl;
            }
        }
        __syncthreads();
        if ((unsigned)ir >= 256u) continue;

#pragma unroll
        for (int dx = 0; dx < 3; dx++) {
#pragma unroll
            for (int kc = 0; kc < CIN / 16; kc++) {
                uint32_t ah[4], al[4];
                const uint32_t abase = (uint32_t)(m0 + dx) * ASTR + kc * 32 + aRowOff;
                ldm4(ah, sAhi + abase);
                ldm4(al, sAlo + abase);
#pragma unroll
                for (int r = 0; r < 4; r++) {
                    const int dy = s - r;
                    if (dy < 0 || dy > 2) continue;
                    const uint32_t kb = (uint32_t)(dy * 3 * CIN + dx * CIN + kc * 16) * 2;
#pragma unroll
                    for (int nt = 0; nt < 4; nt++) {
                        const uint32_t ba = bOff + (uint32_t)nt * 8 * BSTR + kb;
                        uint32_t bh0 = lds32(sBhi + ba), bh1 = lds32(sBhi + ba + 16);
                        uint32_t bl0 = lds32(sBlo + ba), bl1 = lds32(sBlo + ba + 16);
                        mma16816(acc[r] + nt * 4, ah, bh0, bh1);
                        mma16816(acc[r] + nt * 4, al, bh0, bh1);
                        mma16816(acc[r] + nt * 4, ah, bl0, bl1);
                    }
                }
            }
        }
    }

    // epilogue (4 rows)
    const int prow = m0 + (lane >> 2);
#pragma unroll
    for (int r = 0; r < 4; r++) {
        const int h = h0 + r;
        if (!FUSE) {
            float* ob = out + ((size_t)b * HW + (size_t)h * 256 + w0) * 32;
#pragma unroll
            for (int nt = 0; nt < 4; nt++) {
                int ch = nt * 8 + (lane & 3) * 2;
                *(float2*)(ob + (size_t)prow * 32 + ch)       = make_float2(acc[r][nt * 4 + 0], acc[r][nt * 4 + 1]);
                *(float2*)(ob + (size_t)(prow + 8) * 32 + ch) = make_float2(acc[r][nt * 4 + 2], acc[r][nt * 4 + 3]);
            }
        } else {
            float s0v = 0.f, s1v = 0.f;
#pragma unroll
            for (int nt = 0; nt < 4; nt++) {
                int ch = nt * 8 + (lane & 3) * 2;
                float wa = __ldg(&wout[ch]), wb2 = __ldg(&wout[ch + 1]);
                s0v += fmaxf(acc[r][nt * 4 + 0], 0.f) * wa + fmaxf(acc[r][nt * 4 + 1], 0.f) * wb2;
                s1v += fmaxf(acc[r][nt * 4 + 2], 0.f) * wa + fmaxf(acc[r][nt * 4 + 3], 0.f) * wb2;
            }
            s0v += __shfl_xor_sync(0xffffffffu, s0v, 1);
            s0v += __shfl_xor_sync(0xffffffffu, s0v, 2);
            s1v += __shfl_xor_sync(0xffffffffu, s1v, 1);
            s1v += __shfl_xor_sync(0xffffffffu, s1v, 2);
            if ((lane & 3) == 0) {
                size_t ob = (size_t)b * HW + (size_t)h * 256 + w0;
                out[ob + prow]     = 1.0f / (1.0f + expf(-s0v));
                out[ob + prow + 8] = 1.0f / (1.0f + expf(-s1v));
            }
        }
    }
}

// ---------------------------------------------------------------------------
// IRNN: all 4 directional scans in ONE kernel (blockIdx.y = direction).
// NHWC fp32 in (32 ch) -> bf16 hi/lo NHWC 128ch at direction's channel slot.
// ---------------------------------------------------------------------------
template<bool REV>
__device__ __forceinline__
void scan_h_body(const float* __restrict__ in, __nv_bfloat16* __restrict__ ohi,
                 __nv_bfloat16* __restrict__ olo, float wc, float bc, int c, int ch_off)
{
    int t = blockIdx.x * 256 + threadIdx.x;      // over B*W*C = 65536
    int w = (t >> 5) & 255, b = t >> 13;
    const float* ip = in + (size_t)b * HW * 32 + (size_t)w * 32 + c;
    size_t ob = (size_t)b * HW * 128 + (size_t)w * 128 + ch_off + c;

    float hst = REV ? ip[(size_t)255 * 8192] : ip[0];
    {
        size_t o = ob + (size_t)(REV ? 255 : 0) * 32768;
        __nv_bfloat16 hi = __float2bfloat16(hst);
        ohi[o] = hi; olo[o] = __float2bfloat16(hst - __bfloat162float(hi));
    }
#pragma unroll 8
    for (int i = 1; i < 256; i++) {
        int y = REV ? (255 - i) : i;
        hst = fmaxf(wc * hst + bc + ip[(size_t)y * 8192], 0.f);
        size_t o = ob + (size_t)y * 32768;
        __nv_bfloat16 hi = __float2bfloat16(hst);
        ohi[o] = hi; olo[o] = __float2bfloat16(hst - __bfloat162float(hi));
    }
}

template<bool REV>
__device__ __forceinline__
void scan_w_body(const float* __restrict__ in, __nv_bfloat16* __restrict__ ohi,
                 __nv_bfloat16* __restrict__ olo, float wc, float bc, int c, int ch_off)
{
    int t = blockIdx.x * 256 + threadIdx.x;      // over B*H*C = 65536
    int h = (t >> 5) & 255, b = t >> 13;
    const float* ip = in + (size_t)b * HW * 32 + (size_t)h * 8192 + c;
    size_t ob = (size_t)b * HW * 128 + (size_t)h * 32768 + ch_off + c;

    float hst = REV ? ip[255 * 32] : ip[0];
    {
        size_t o = ob + (size_t)(REV ? 255 : 0) * 128;
        __nv_bfloat16 hi = __float2bfloat16(hst);
        ohi[o] = hi; olo[o] = __float2bfloat16(hst - __bfloat162float(hi));
    }
#pragma unroll 8
    for (int i = 1; i < 256; i++) {
        int w = REV ? (255 - i) : i;
        hst = fmaxf(wc * hst + bc + ip[w * 32], 0.f);
        size_t o = ob + (size_t)w * 128;
        __nv_bfloat16 hi = __float2bfloat16(hst);
        ohi[o] = hi; olo[o] = __float2bfloat16(hst - __bfloat162float(hi));
    }
}

__global__ __launch_bounds__(256)
void scan_all(const float* __restrict__ in, __nv_bfloat16* __restrict__ ohi,
              __nv_bfloat16* __restrict__ olo, const float* __restrict__ ws,
              const float* __restrict__ bs)
{
    const int d = blockIdx.y;
    const int c = threadIdx.x & 31;
    const float wc = ws[d * 32 + c], bc = bs[d * 32 + c];
    if      (d == 0) scan_h_body<true >(in, ohi, olo, wc, bc, c, 0);    // up
    else if (d == 1) scan_w_body<false>(in, ohi, olo, wc, bc, c, 32);   // right
    else if (d == 2) scan_h_body<false>(in, ohi, olo, wc, bc, c, 64);   // down
    else             scan_w_body<true >(in, ohi, olo, wc, bc, c, 96);   // left
}

// ---------------------------------------------------------------------------
extern "C" void kernel_launch(void* const* d_in, const int* in_sizes, int n_in,
                              void* d_out, int out_size)
{
    const float* x   = (const float*)d_in[0];
    const float* w1  = (const float*)d_in[1];
    const float* w2  = (const float*)d_in[2];
    const float* w3  = (const float*)d_in[3];
    const float* wo  = (const float*)d_in[4];
    const float* i1w = (const float*)d_in[5];
    const float* i1b = (const float*)d_in[6];
    const float* i2w = (const float*)d_in[7];
    const float* i2b = (const float*)d_in[8];
    float* outp = (float*)d_out;

    float* gf;  __nv_bfloat16 *ghi, *glo;  char* gwb;
    cudaGetSymbolAddress((void**)&gf,  g_f32);
    cudaGetSymbolAddress((void**)&ghi, g_hi);
    cudaGetSymbolAddress((void**)&glo, g_lo);
    cudaGetSymbolAddress((void**)&gwb, g_wb);

    // smem: conv1 = 2*18944 + 2*10400 = 58688 ; conv2/3 = 2*74240 + 2*35360 = 219200
    cudaFuncSetAttribute(conv_mma<32,  false>, cudaFuncAttributeMaxDynamicSharedMemorySize, 58688);
    cudaFuncSetAttribute(conv_mma<128, false>, cudaFuncAttributeMaxDynamicSharedMemorySize, 219200);
    cudaFuncSetAttribute(conv_mma<128, true >, cudaFuncAttributeMaxDynamicSharedMemorySize, 219200);

    // prep B weight images
    prep_w<<<(32 * 296  + 255) / 256, 256>>>(w1, gwb + 0,      gwb + 18944,  32);
    prep_w<<<(32 * 1160 + 255) / 256, 256>>>(w2, gwb + 37888,  gwb + 112128, 128);
    prep_w<<<(32 * 1160 + 255) / 256, 256>>>(w3, gwb + 186368, gwb + 260608, 128);

    // x -> NHWC bf16 split (32 ch)
    transpose_x<<<dim3(2048, 8), 256>>>(x, ghi, glo);

    dim3 cg(2, 64, 8);   // 4 output rows per CTA
    conv_mma<32, false><<<cg, 256, 58688>>>(ghi, glo, gwb + 0, nullptr, gf);

    scan_all<<<dim3(256, 4), 256>>>(gf, ghi, glo, i1w, i1b);

    conv_mma<128, false><<<cg, 256, 219200>>>(ghi, glo, gwb + 37888, nullptr, gf);

    scan_all<<<dim3(256, 4), 256>>>(gf, ghi, glo, i2w, i2b);

    conv_mma<128, true><<<cg, 256, 219200>>>(ghi, glo, gwb + 186368, wo, outp);
}

// round 7
// speedup vs baseline: 4.3927x; 1.2167x over previous
#include <cuda_runtime.h>
#include <cuda_bf16.h>
#include <math.h>
#include <stdint.h>

#define HW 65536

// ---------------------------------------------------------------------------
// Scratch (no allocations allowed)
// ---------------------------------------------------------------------------
__device__ float          g_f32[8ULL * 65536 * 32];    //  64 MB NHWC fp32 conv outputs
__device__ __nv_bfloat16  g_hi [8ULL * 65536 * 128];   // 128 MB NHWC bf16 hi
__device__ __nv_bfloat16  g_lo [8ULL * 65536 * 128];   // 128 MB NHWC bf16 lo
__device__ __align__(16) char g_wb[334848];            // prepped B (padded row-major, hi|lo)
// conv1: hi@0      lo@18944   (BSTR=592,  32 rows)
// conv2: hi@37888  lo@112128  (BSTR=2320, 32 rows)
// conv3: hi@186368 lo@260608

// ---------------------------------------------------------------------------
__device__ __forceinline__ uint32_t smem_u32(const void* p) {
    uint32_t a;
    asm("{ .reg .u64 t; cvta.to.shared.u64 t, %1; cvt.u32.u64 %0, t; }" : "=r"(a) : "l"(p));
    return a;
}
__device__ __forceinline__ void ldm4(uint32_t* r, uint32_t a) {
    asm volatile("ldmatrix.sync.aligned.m8n8.x4.shared.b16 {%0,%1,%2,%3}, [%4];"
                 : "=r"(r[0]), "=r"(r[1]), "=r"(r[2]), "=r"(r[3]) : "r"(a));
}
__device__ __forceinline__ void mma16816(float* c, const uint32_t* a, uint32_t b0, uint32_t b1) {
    asm volatile("mma.sync.aligned.m16n8k16.row.col.f32.bf16.bf16.f32 "
        "{%0,%1,%2,%3}, {%4,%5,%6,%7}, {%8,%9}, {%0,%1,%2,%3};"
        : "+f"(c[0]), "+f"(c[1]), "+f"(c[2]), "+f"(c[3])
        : "r"(a[0]), "r"(a[1]), "r"(a[2]), "r"(a[3]), "r"(b0), "r"(b1));
}
__device__ __forceinline__ void cp16(uint32_t saddr, const void* gaddr, int sz) {
    asm volatile("cp.async.cg.shared.global [%0], [%1], 16, %2;"
                 :: "r"(saddr), "l"(gaddr), "r"(sz));
}
__device__ __forceinline__ void cp_commit_wait() {
    asm volatile("cp.async.commit_group;");
    asm volatile("cp.async.wait_group 0;");
}

// ---------------------------------------------------------------------------
// Weight prep: fp32 [32][CIN][3][3] -> bf16 hi/lo padded row-major B images.
// ---------------------------------------------------------------------------
__global__ void prep_w(const float* __restrict__ w, char* __restrict__ bhi,
                       char* __restrict__ blo, int CIN)
{
    int K = 9 * CIN, KP = K + 8, BSTR = K * 2 + 16;
    int idx = blockIdx.x * 256 + threadIdx.x;
    if (idx >= 32 * KP) return;
    int n = idx / KP, k = idx - n * KP;
    float v = 0.f;
    if (k < K) {
        int dyi = k / (3 * CIN);
        int r   = k - dyi * 3 * CIN;
        int dxi = r / CIN;
        int c   = r - dxi * CIN;
        v = w[(n * CIN + c) * 9 + dyi * 3 + dxi];
    }
    __nv_bfloat16 hi = __float2bfloat16(v);
    __nv_bfloat16 lo = __float2bfloat16(v - __bfloat162float(hi));
    int o = n * BSTR + k * 2;
    *(__nv_bfloat16*)(bhi + o) = hi;
    *(__nv_bfloat16*)(blo + o) = lo;
}

// ---------------------------------------------------------------------------
// x (NCHW fp32) -> NHWC bf16 hi/lo (32 ch)
// ---------------------------------------------------------------------------
__global__ __launch_bounds__(256)
void transpose_x(const float* __restrict__ x, __nv_bfloat16* __restrict__ ohi,
                 __nv_bfloat16* __restrict__ olo)
{
    __shared__ float t[32][33];
    int b = blockIdx.y;
    int p0 = blockIdx.x * 32;
    int lane = threadIdx.x & 31, grp = threadIdx.x >> 5;
#pragma unroll
    for (int i = 0; i < 4; i++) {
        int c = grp + i * 8;
        t[c][lane] = x[((size_t)b * 32 + c) * HW + p0 + lane];
    }
    __syncthreads();
#pragma unroll
    for (int i = 0; i < 4; i++) {
        int p = grp + i * 8;
        float v = t[lane][p];
        __nv_bfloat16 hi = __float2bfloat16(v);
        __nv_bfloat16 lo = __float2bfloat16(v - __bfloat162float(hi));
        size_t o = ((size_t)b * HW + p0 + p) * 32 + lane;
        ohi[o] = hi; olo[o] = lo;
    }
}

// ---------------------------------------------------------------------------
// HMMA implicit-GEMM 3x3 conv, 4 output rows per CTA.
// A staged per input row via cp.async; B fragments via ldmatrix.x4.
// Split-3: acc += Ahi*Bhi + Alo*Bhi + Ahi*Blo (fp32 accumulators).
// ---------------------------------------------------------------------------
template<int CIN, bool FUSE>
__global__ __launch_bounds__(256, 1)
void conv_mma(const __nv_bfloat16* __restrict__ ahi, const __nv_bfloat16* __restrict__ alo,
              const char* __restrict__ wb, const float* __restrict__ wout,
              float* __restrict__ out)
{
    constexpr int K     = 9 * CIN;
    constexpr int ASTR  = CIN * 2 + 16;        // A row stride (bytes)
    constexpr int BSTR  = K * 2 + 16;          // B row stride (bytes)
    constexpr int BBYT  = 32 * BSTR;           // one split's B image
    constexpr int V4    = CIN / 8;             // uint4 per pixel-row
    constexpr int ABYT  = 130 * ASTR;          // one input row (one split)

    extern __shared__ __align__(16) char smem[];
    // [Bhi BBYT][Blo BBYT][Ahi ABYT][Alo ABYT]
    const int tid  = threadIdx.x;
    const int lane = tid & 31;
    const int wid  = tid >> 5;
    const int w0   = blockIdx.x << 7;
    const int h0   = blockIdx.y << 2;          // first of 4 output rows
    const int b    = blockIdx.z;

    const uint32_t s0   = smem_u32(smem);
    const uint32_t sBhi = s0;
    const uint32_t sBlo = s0 + BBYT;
    const uint32_t sAhi = s0 + 2 * BBYT;
    const uint32_t sAlo = sAhi + ABYT;

    // copy B (hi|lo contiguous) into smem via cp.async
    {
        const char* src = wb;
        const int n4 = 2 * BBYT / 16;
        for (int i = tid; i < n4; i += 256)
            cp16(s0 + i * 16, src + i * 16, 16);
        cp_commit_wait();
    }

    const int m0 = wid * 16;
    const uint32_t aRowOff = (uint32_t)(lane & 15) * ASTR + ((lane & 16) ? 16u : 0u);
    // B ldmatrix lane address: n = (lane&7) + (lane>=16 ? 8:0), koff = ((lane>>3)&1)*16
    const uint32_t bLM = (uint32_t)((lane & 7) + ((lane & 16) ? 8 : 0)) * BSTR
                       + (uint32_t)((lane >> 3) & 1) * 16;

    float acc[4][16];
#pragma unroll
    for (int r = 0; r < 4; r++)
#pragma unroll
        for (int i = 0; i < 16; i++) acc[r][i] = 0.f;

    for (int s = 0; s < 6; s++) {
        const int ir = h0 - 1 + s;                 // input row
        __syncthreads();
        if ((unsigned)ir < 256u) {
            // stage A row [130 px][CIN] hi+lo with zero-fill w-halo via cp.async
            const size_t rowbase = ((size_t)b * HW + (size_t)ir * 256);
            for (int i = tid; i < 130 * V4; i += 256) {
                int px = i / V4, v = i - px * V4;
                int w  = w0 - 1 + px;
                int ok = ((unsigned)w < 256u);
                int wc = ok ? w : 0;
                const void* gh = (const char*)(ahi + (rowbase + wc) * CIN) + v * 16;
                const void* gl = (const char*)(alo + (rowbase + wc) * CIN) + v * 16;
                uint32_t d = (uint32_t)(px * ASTR + v * 16);
                cp16(sAhi + d, gh, ok ? 16 : 0);
                cp16(sAlo + d, gl, ok ? 16 : 0);
            }
            cp_commit_wait();
        }
        __syncthreads();
        if ((unsigned)ir >= 256u) continue;

#pragma unroll
        for (int r = 0; r < 4; r++) {
            const int dy = s - r;
            if (dy < 0 || dy > 2) continue;
#pragma unroll
            for (int dx = 0; dx < 3; dx++) {
#pragma unroll
                for (int kc = 0; kc < CIN / 16; kc++) {
                    uint32_t ah[4], al[4];
                    const uint32_t abase = (uint32_t)(m0 + dx) * ASTR + kc * 32 + aRowOff;
                    ldm4(ah, sAhi + abase);
                    ldm4(al, sAlo + abase);
                    const uint32_t kb = (uint32_t)(dy * 3 * CIN + dx * CIN + kc * 16) * 2;
                    uint32_t bh[4], bh2[4], bl[4], bl2[4];
                    ldm4(bh,  sBhi + bLM + kb);                 // n0-15
                    ldm4(bh2, sBhi + bLM + kb + 16 * BSTR);     // n16-31
                    ldm4(bl,  sBlo + bLM + kb);
                    ldm4(bl2, sBlo + bLM + kb + 16 * BSTR);
                    float* a0 = acc[r];
                    mma16816(a0 + 0,  ah, bh[0],  bh[1]);
                    mma16816(a0 + 4,  ah, bh[2],  bh[3]);
                    mma16816(a0 + 8,  ah, bh2[0], bh2[1]);
                    mma16816(a0 + 12, ah, bh2[2], bh2[3]);
                    mma16816(a0 + 0,  al, bh[0],  bh[1]);
                    mma16816(a0 + 4,  al, bh[2],  bh[3]);
                    mma16816(a0 + 8,  al, bh2[0], bh2[1]);
                    mma16816(a0 + 12, al, bh2[2], bh2[3]);
                    mma16816(a0 + 0,  ah, bl[0],  bl[1]);
                    mma16816(a0 + 4,  ah, bl[2],  bl[3]);
                    mma16816(a0 + 8,  ah, bl2[0], bl2[1]);
                    mma16816(a0 + 12, ah, bl2[2], bl2[3]);
                }
            }
        }
    }

    // epilogue (4 rows)
    const int prow = m0 + (lane >> 2);
#pragma unroll
    for (int r = 0; r < 4; r++) {
        const int h = h0 + r;
        if (!FUSE) {
            float* ob = out + ((size_t)b * HW + (size_t)h * 256 + w0) * 32;
#pragma unroll
            for (int nt = 0; nt < 4; nt++) {
                int ch = nt * 8 + (lane & 3) * 2;
                *(float2*)(ob + (size_t)prow * 32 + ch)       = make_float2(acc[r][nt * 4 + 0], acc[r][nt * 4 + 1]);
                *(float2*)(ob + (size_t)(prow + 8) * 32 + ch) = make_float2(acc[r][nt * 4 + 2], acc[r][nt * 4 + 3]);
            }
        } else {
            float s0v = 0.f, s1v = 0.f;
#pragma unroll
            for (int nt = 0; nt < 4; nt++) {
                int ch = nt * 8 + (lane & 3) * 2;
                float wa = __ldg(&wout[ch]), wb2 = __ldg(&wout[ch + 1]);
                s0v += fmaxf(acc[r][nt * 4 + 0], 0.f) * wa + fmaxf(acc[r][nt * 4 + 1], 0.f) * wb2;
                s1v += fmaxf(acc[r][nt * 4 + 2], 0.f) * wa + fmaxf(acc[r][nt * 4 + 3], 0.f) * wb2;
            }
            s0v += __shfl_xor_sync(0xffffffffu, s0v, 1);
            s0v += __shfl_xor_sync(0xffffffffu, s0v, 2);
            s1v += __shfl_xor_sync(0xffffffffu, s1v, 1);
            s1v += __shfl_xor_sync(0xffffffffu, s1v, 2);
            if ((lane & 3) == 0) {
                size_t ob = (size_t)b * HW + (size_t)h * 256 + w0;
                out[ob + prow]     = 1.0f / (1.0f + expf(-s0v));
                out[ob + prow + 8] = 1.0f / (1.0f + expf(-s1v));
            }
        }
    }
}

// ---------------------------------------------------------------------------
// IRNN: all 4 directional scans in ONE kernel (blockIdx.y = direction).
// ---------------------------------------------------------------------------
template<bool REV>
__device__ __forceinline__
void scan_h_body(const float* __restrict__ in, __nv_bfloat16* __restrict__ ohi,
                 __nv_bfloat16* __restrict__ olo, float wc, float bc, int c, int ch_off)
{
    int t = blockIdx.x * 256 + threadIdx.x;      // over B*W*C = 65536
    int w = (t >> 5) & 255, b = t >> 13;
    const float* ip = in + (size_t)b * HW * 32 + (size_t)w * 32 + c;
    size_t ob = (size_t)b * HW * 128 + (size_t)w * 128 + ch_off + c;

    float hst = REV ? ip[(size_t)255 * 8192] : ip[0];
    {
        size_t o = ob + (size_t)(REV ? 255 : 0) * 32768;
        __nv_bfloat16 hi = __float2bfloat16(hst);
        ohi[o] = hi; olo[o] = __float2bfloat16(hst - __bfloat162float(hi));
    }
#pragma unroll 8
    for (int i = 1; i < 256; i++) {
        int y = REV ? (255 - i) : i;
        hst = fmaxf(wc * hst + bc + ip[(size_t)y * 8192], 0.f);
        size_t o = ob + (size_t)y * 32768;
        __nv_bfloat16 hi = __float2bfloat16(hst);
        ohi[o] = hi; olo[o] = __float2bfloat16(hst - __bfloat162float(hi));
    }
}

template<bool REV>
__device__ __forceinline__
void scan_w_body(const float* __restrict__ in, __nv_bfloat16* __restrict__ ohi,
                 __nv_bfloat16* __restrict__ olo, float wc, float bc, int c, int ch_off)
{
    int t = blockIdx.x * 256 + threadIdx.x;      // over B*H*C = 65536
    int h = (t >> 5) & 255, b = t >> 13;
    const float* ip = in + (size_t)b * HW * 32 + (size_t)h * 8192 + c;
    size_t ob = (size_t)b * HW * 128 + (size_t)h * 32768 + ch_off + c;

    float hst = REV ? ip[255 * 32] : ip[0];
    {
        size_t o = ob + (size_t)(REV ? 255 : 0) * 128;
        __nv_bfloat16 hi = __float2bfloat16(hst);
        ohi[o] = hi; olo[o] = __float2bfloat16(hst - __bfloat162float(hi));
    }
#pragma unroll 8
    for (int i = 1; i < 256; i++) {
        int w = REV ? (255 - i) : i;
        hst = fmaxf(wc * hst + bc + ip[w * 32], 0.f);
        size_t o = ob + (size_t)w * 128;
        __nv_bfloat16 hi = __float2bfloat16(hst);
        ohi[o] = hi; olo[o] = __float2bfloat16(hst - __bfloat162float(hi));
    }
}

__global__ __launch_bounds__(256)
void scan_all(const float* __restrict__ in, __nv_bfloat16* __restrict__ ohi,
              __nv_bfloat16* __restrict__ olo, const float* __restrict__ ws,
              const float* __restrict__ bs)
{
    const int d = blockIdx.y;
    const int c = threadIdx.x & 31;
    const float wc = ws[d * 32 + c], bc = bs[d * 32 + c];
    if      (d == 0) scan_h_body<true >(in, ohi, olo, wc, bc, c, 0);    // up
    else if (d == 1) scan_w_body<false>(in, ohi, olo, wc, bc, c, 32);   // right
    else if (d == 2) scan_h_body<false>(in, ohi, olo, wc, bc, c, 64);   // down
    else             scan_w_body<true >(in, ohi, olo, wc, bc, c, 96);   // left
}

// ---------------------------------------------------------------------------
extern "C" void kernel_launch(void* const* d_in, const int* in_sizes, int n_in,
                              void* d_out, int out_size)
{
    const float* x   = (const float*)d_in[0];
    const float* w1  = (const float*)d_in[1];
    const float* w2  = (const float*)d_in[2];
    const float* w3  = (const float*)d_in[3];
    const float* wo  = (const float*)d_in[4];
    const float* i1w = (const float*)d_in[5];
    const float* i1b = (const float*)d_in[6];
    const float* i2w = (const float*)d_in[7];
    const float* i2b = (const float*)d_in[8];
    float* outp = (float*)d_out;

    float* gf;  __nv_bfloat16 *ghi, *glo;  char* gwb;
    cudaGetSymbolAddress((void**)&gf,  g_f32);
    cudaGetSymbolAddress((void**)&ghi, g_hi);
    cudaGetSymbolAddress((void**)&glo, g_lo);
    cudaGetSymbolAddress((void**)&gwb, g_wb);

    // smem: conv1 = 2*18944 + 2*10400 = 58688 ; conv2/3 = 2*74240 + 2*35360 = 219200
    cudaFuncSetAttribute(conv_mma<32,  false>, cudaFuncAttributeMaxDynamicSharedMemorySize, 58688);
    cudaFuncSetAttribute(conv_mma<128, false>, cudaFuncAttributeMaxDynamicSharedMemorySize, 219200);
    cudaFuncSetAttribute(conv_mma<128, true >, cudaFuncAttributeMaxDynamicSharedMemorySize, 219200);

    // prep B weight images
    prep_w<<<(32 * 296  + 255) / 256, 256>>>(w1, gwb + 0,      gwb + 18944,  32);
    prep_w<<<(32 * 1160 + 255) / 256, 256>>>(w2, gwb + 37888,  gwb + 112128, 128);
    prep_w<<<(32 * 1160 + 255) / 256, 256>>>(w3, gwb + 186368, gwb + 260608, 128);

    // x -> NHWC bf16 split (32 ch)
    transpose_x<<<dim3(2048, 8), 256>>>(x, ghi, glo);

    dim3 cg(2, 64, 8);   // 4 output rows per CTA
    conv_mma<32, false><<<cg, 256, 58688>>>(ghi, glo, gwb + 0, nullptr, gf);

    scan_all<<<dim3(256, 4), 256>>>(gf, ghi, glo, i1w, i1b);

    conv_mma<128, false><<<cg, 256, 219200>>>(ghi, glo, gwb + 37888, nullptr, gf);

    scan_all<<<dim3(256, 4), 256>>>(gf, ghi, glo, i2w, i2b);

    conv_mma<128, true><<<cg, 256, 219200>>>(ghi, glo, gwb + 186368, wo, outp);
}